// round 16
// baseline (speedup 1.0000x reference)
#include <cuda_runtime.h>
#include <math.h>
#include <stdint.h>

// ---------------------------------------------------------------------------
// SPFBlock fused kernel v10, sm_103 (portable PTX) — mma.sync m16n8k8 tf32.
// v10 = v9 + vectorized fragment fetches:
//  - pos-interleaved t/pf layout -> A fragments via LDS.64 (stride 72)
//  - k-interleaved B (permuted in k_init) -> B fragments via LDS.64 (stride 72)
//  - ij table: one uint4 per warp per chunk instead of 8 scattered __ldg
// ---------------------------------------------------------------------------

#define BATCH   4
#define CIN     128
#define LTOT    16384
#define NHEAD   4
#define NPH     32
#define MTRI    528
#define CPOOL   2112
#define DIMO    64
#define NCHUNK  33              // 33 * 64 = 2112
#define POSB    64              // positions per block

// smem float offsets (k_main)
#define FT      0               // t tile [128c][64p] (pos-interleaved)   8192
#define FPF     8192            // pf 2 x [64k][72]                       9216
#define FB      17408           // B  2 x [64n][72]                       9216
#define FS      26624           // scales 256
#define FP      26880           // params 256
#define FTOT    27136           // 108544 bytes

#define PFBUF   4608            // floats per pf buffer (64*72)
#define BBUF    4608            // floats per B buffer  (64*72)

// ------------------------- device scratch (static) -------------------------
__device__ float g_t[BATCH * CIN * LTOT];       // shuffled LN'd t, [b][c][pos]
__device__ float g_e[BATCH * LTOT * NHEAD];     // exp(logit)
__device__ float g_wNk[DIMO * CPOOL];           // tf32 dr_w, [n][kappa(k)]
__device__ float g_fc1T[DIMO * DIMO];           // fc1_w transposed [c][j]
__device__ float g_umid[BATCH * CIN];
__device__ float g_invnmid[BATCH * NHEAD];
__device__ float g_sumexp[BATCH * NHEAD];
__device__ uchar2 g_ij[CPOOL];

// ------------------------------ PTX helpers --------------------------------
__device__ __forceinline__ uint32_t cvt_tf32(float x) {
    uint32_t r;
    asm("cvt.rna.tf32.f32 %0, %1;" : "=r"(r) : "f"(x));
    return r;
}
__device__ __forceinline__ void mma8(float* d, const uint32_t* a, const uint32_t* b) {
    asm volatile(
        "mma.sync.aligned.m16n8k8.row.col.f32.tf32.tf32.f32 "
        "{%0,%1,%2,%3}, {%4,%5,%6,%7}, {%8,%9}, {%0,%1,%2,%3};"
        : "+f"(d[0]), "+f"(d[1]), "+f"(d[2]), "+f"(d[3])
        : "r"(a[0]), "r"(a[1]), "r"(a[2]), "r"(a[3]), "r"(b[0]), "r"(b[1]));
}

// ------------------------------- init kernel -------------------------------
__global__ void k_init(const float* __restrict__ dr_w,
                       const float* __restrict__ fc1_w) {
    int tid = blockIdx.x * blockDim.x + threadIdx.x;
    int nth = gridDim.x * blockDim.x;
    // B with kappa(k) interleave: pairs (k, k+4) adjacent within each group of 8
    for (int idx = tid; idx < DIMO * CPOOL; idx += nth) {
        int n = idx / CPOOL, k = idx % CPOOL;
        int kp = (k & ~7) | ((k & 3) << 1) | ((k >> 2) & 1);
        g_wNk[n * CPOOL + kp] = __uint_as_float(cvt_tf32(dr_w[idx]));
    }
    for (int idx = tid; idx < DIMO * DIMO; idx += nth) {
        int c = idx >> 6, j = idx & 63;
        g_fc1T[idx] = fc1_w[j * DIMO + c];
    }
    if (blockIdx.x == 0) {
        for (int m = threadIdx.x; m < MTRI; m += blockDim.x) {
            int i = 0, off = 0;
            while (off + (NPH - i) <= m) { off += NPH - i; i++; }
            int j = i + (m - off);
            #pragma unroll
            for (int h = 0; h < NHEAD; h++) {
                uchar2 v;
                v.x = (unsigned char)(h * NPH + i);
                v.y = (unsigned char)(h * NPH + j);
                g_ij[h * MTRI + m] = v;
            }
        }
        if (threadIdx.x < BATCH * NHEAD) g_sumexp[threadIdx.x] = 0.0f;
    }
}

// ------------------------------- mid kernel --------------------------------
__global__ void k_mid(const float* __restrict__ x,
                      const float* __restrict__ n1w,
                      const float* __restrict__ n1b) {
    __shared__ float red[CIN];
    __shared__ float us[CIN];
    int b = blockIdx.x, tid = threadIdx.x;
    float v = x[((size_t)b * CIN + tid) * LTOT + (LTOT / 2)];
    red[tid] = v;
    __syncthreads();
    for (int o = 64; o; o >>= 1) { if (tid < o) red[tid] += red[tid + o]; __syncthreads(); }
    float mu = red[0] * (1.0f / 128.0f);
    __syncthreads();
    red[tid] = v * v;
    __syncthreads();
    for (int o = 64; o; o >>= 1) { if (tid < o) red[tid] += red[tid + o]; __syncthreads(); }
    float var = red[0] * (1.0f / 128.0f) - mu * mu;
    float rstd = rsqrtf(var + 1e-5f);
    float xn = (v - mu) * rstd * n1w[tid] + n1b[tid];
    int cp = ((tid & 3) << 5) + (tid >> 2);
    us[cp] = xn;
    g_umid[b * CIN + cp] = xn;
    __syncthreads();
    if (tid < NHEAD) {
        float uu = 0.f, s4 = 0.f;
        #pragma unroll
        for (int i = 0; i < NPH; i++) {
            float u = us[tid * NPH + i];
            float u2 = u * u;
            uu += u2; s4 += u2 * u2;
        }
        g_invnmid[b * NHEAD + tid] = rsqrtf(0.5f * (uu * uu + s4));
    }
}

// -------------------------------- LN kernel --------------------------------
__global__ void k_ln(const float* __restrict__ x,
                     const float* __restrict__ n1w,
                     const float* __restrict__ n1b) {
    extern __shared__ float sm[];
    float* xs   = sm;                       // 128*129
    float* su   = sm + 128 * 129;
    float* swv  = su + 128;
    float* sbv  = swv + 128;
    float* sAcc = sbv + 128;

    int tid = threadIdx.x;
    int blk = blockIdx.x;
    int b   = blk >> 7;
    int p0  = (blk & 127) << 7;

    su[tid] = g_umid[b * CIN + tid];
    {
        int c = ((tid & 31) << 2) + (tid >> 5);
        swv[tid] = n1w[c];
        sbv[tid] = n1b[c];
    }
    if (tid < NHEAD) sAcc[tid] = 0.0f;

    const float* xb = x + (size_t)b * CIN * LTOT + p0;
    #pragma unroll 4
    for (int cc = 0; cc < CIN; cc++) {
        float v = xb[(size_t)cc * LTOT + tid];
        int cp = ((cc & 3) << 5) + (cc >> 2);
        xs[tid * 129 + cp] = v;
    }
    __syncthreads();

    float* row = xs + tid * 129;
    float s = 0.f, s2 = 0.f;
    #pragma unroll 8
    for (int c = 0; c < CIN; c++) { float v = row[c]; s += v; s2 += v * v; }
    float mu   = s  * (1.0f / 128.0f);
    float var  = s2 * (1.0f / 128.0f) - mu * mu;
    float rstd = rsqrtf(var + 1e-5f);

    int gp = b * LTOT + p0 + tid;
    #pragma unroll
    for (int h = 0; h < NHEAD; h++) {
        float duv = 0.f, dvv = 0.f, suv = 0.f, sv4 = 0.f;
        #pragma unroll 8
        for (int i = 0; i < NPH; i++) {
            int c = h * NPH + i;
            float v = (row[c] - mu) * rstd * swv[c] + sbv[c];
            row[c] = v;
            float u  = su[c];
            float uv = u * v;
            float v2 = v * v;
            duv += uv; dvv += v2; suv += uv * uv; sv4 += v2 * v2;
        }
        float ny2   = 0.5f * (dvv * dvv + sv4);
        float logit = 0.5f * (duv * duv + suv) * rsqrtf(ny2) * g_invnmid[b * NHEAD + h];
        float e = expf(logit);
        g_e[gp * NHEAD + h] = e;
        float we = e;
        #pragma unroll
        for (int o = 16; o; o >>= 1) we += __shfl_xor_sync(0xffffffffu, we, o);
        if ((tid & 31) == 0) atomicAdd(&sAcc[h], we);
    }
    __syncthreads();
    if (tid < NHEAD) atomicAdd(&g_sumexp[b * NHEAD + tid], sAcc[tid]);

    float* tb = g_t + (size_t)b * CIN * LTOT + p0;
    #pragma unroll 4
    for (int c = 0; c < CIN; c++) {
        tb[(size_t)c * LTOT + tid] = xs[tid * 129 + c];
    }
}

// ------------------------------- main kernel -------------------------------
// 64 pos x 64 out per block, 256 threads (8 warps), 2 blocks/SM.
// Warp w: m-group w&1 (2 m16), n-group (w>>1)&1 (4 n8), k-half w>>2.
// t/pf pos-interleaved (rows r, r+8 adjacent); B k-interleaved (k, k+4).
__global__ __launch_bounds__(256, 2)
void k_main(const float* __restrict__ dr_b,  const float* __restrict__ n2w,
            const float* __restrict__ n2b,   const float* __restrict__ fc1_b,
            float* __restrict__ out) {
    extern __shared__ float sm[];
    float* sT = sm + FT;                 // [128c][64p'] pos-interleaved
    float* sB = sm + FB;                 // 2 x [64n][72k']
    float* sS = sm + FS;
    float* sP = sm + FP;
    uint32_t* pfu = (uint32_t*)(sm + FPF);   // 2 x [64k][72p']

    int tid  = threadIdx.x;
    int lane = tid & 31, w = tid >> 5;
    int gp0  = blockIdx.x << 6;
    int b    = gp0 >> 14;
    int p0   = gp0 & (LTOT - 1);

    // stage scales sqrt(L*attn) and params
    {
        int pos = tid >> 2, h = tid & 3;
        float e = g_e[(gp0 + pos) * NHEAD + h];
        sS[tid] = sqrtf(16384.0f * e / g_sumexp[b * NHEAD + h]);
    }
    if (tid < 64) {
        sP[tid]       = dr_b[tid];
        sP[64 + tid]  = n2w[tid];
        sP[128 + tid] = n2b[tid];
        sP[192 + tid] = fc1_b[tid];
    }
    __syncthreads();

    // stage scaled t [c][pi(p)]: within each 16-group, rows r and r+8 interleave
    {
        const float* tb = g_t + (size_t)b * CIN * LTOT + p0;
        #pragma unroll
        for (int it = 0; it < 4; it++) {
            int u  = tid + (it << 8);         // 0..1023
            int c  = u >> 3;
            int g  = (u >> 1) & 3;
            int r4 = (u & 1) << 2;            // 0 or 4
            int pb = (g << 4) + r4;
            const float* src = tb + (size_t)c * LTOT + pb;
            float4 lo = *(const float4*)(src);
            float4 hi = *(const float4*)(src + 8);
            int hb = c >> 5;
            lo.x *= sS[((pb + 0) << 2) + hb];  hi.x *= sS[((pb + 8)  << 2) + hb];
            lo.y *= sS[((pb + 1) << 2) + hb];  hi.y *= sS[((pb + 9)  << 2) + hb];
            lo.z *= sS[((pb + 2) << 2) + hb];  hi.z *= sS[((pb + 10) << 2) + hb];
            lo.w *= sS[((pb + 3) << 2) + hb];  hi.w *= sS[((pb + 11) << 2) + hb];
            float* dst = sT + (c << 6) + (g << 4) + (r4 << 1);
            *(float4*)(dst)     = make_float4(lo.x, hi.x, lo.y, hi.y);
            *(float4*)(dst + 4) = make_float4(lo.z, hi.z, lo.w, hi.w);
        }
    }
    __syncthreads();

    const int tig  = lane & 3, gid = lane >> 2;
    const int ksel = w >> 2;                 // 0: ksteps 0-3, 1: ksteps 4-7
    const int pbase = (w & 1) << 5;          // word offset of m-group
    const int nbase = ((w >> 1) & 1) << 5;   // 4 n8 tiles
    const int rhalf = lane >> 4;             // build: row within pass
    const int p4l   = (lane & 15) << 2;      // build: float4 word index
    const int sh    = rhalf << 4;            // ij byte shift

    // ---- prologue: stage B(0) + build pf(0) into buffer 0 ----
    {
        #pragma unroll
        for (int i = 0; i < 4; i++) {
            int idx = tid + (i << 8);
            int n = idx >> 4, k4 = (idx & 15) << 2;
            float4 v = *(const float4*)(g_wNk + n * CPOOL + k4);
            *(float4*)(sB + n * 72 + k4) = v;
        }
        uint4 ijp = __ldg((const uint4*)(g_ij + (w << 3)));
        const uint32_t* ijw = (const uint32_t*)&ijp;
        #pragma unroll
        for (int pass = 0; pass < 4; pass++) {
            uint32_t wd = ijw[pass];
            int ii = (wd >> sh) & 0xFF;
            int jj = (wd >> (sh + 8)) & 0xFF;
            int rw = (w << 3) + (pass << 1) + rhalf;
            float4 a4 = *(const float4*)(sT + (ii << 6) + p4l);
            float4 b4 = *(const float4*)(sT + (jj << 6) + p4l);
            uint4 r;
            r.x = cvt_tf32(a4.x * b4.x);
            r.y = cvt_tf32(a4.y * b4.y);
            r.z = cvt_tf32(a4.z * b4.z);
            r.w = cvt_tf32(a4.w * b4.w);
            *(uint4*)(pfu + rw * 72 + p4l) = r;
        }
    }
    __syncthreads();

    float d[2][4][4];
    #pragma unroll
    for (int mt = 0; mt < 2; mt++)
        #pragma unroll
        for (int nt = 0; nt < 4; nt++)
            #pragma unroll
            for (int q = 0; q < 4; q++) d[mt][nt][q] = 0.f;

    // ---- main loop: one barrier per chunk ----
    for (int g = 0; g < NCHUNK; g++) {
        int cur = g & 1, nxt = cur ^ 1;
        uint32_t* pfc = pfu + cur * PFBUF;
        float*    sBc = sB  + cur * BBUF;
        bool more = (g + 1 < NCHUNK);

        // 1. issue LDG for B(g+1) and packed ij(g+1)
        float4 breg[4];
        uint4 ijp = make_uint4(0, 0, 0, 0);
        if (more) {
            const float* wsrc = g_wNk + ((g + 1) << 6);
            #pragma unroll
            for (int i = 0; i < 4; i++) {
                int idx = tid + (i << 8);
                int n = idx >> 4, k4 = (idx & 15) << 2;
                breg[i] = *(const float4*)(wsrc + n * CPOOL + k4);
            }
            ijp = __ldg((const uint4*)(g_ij + ((g + 1) << 6) + (w << 3)));
        }

        // 2. build pf(g+1) into nxt buffer (overlaps mma in issue order)
        if (more) {
            uint32_t* pfn = pfu + nxt * PFBUF;
            const uint32_t* ijw = (const uint32_t*)&ijp;
            #pragma unroll
            for (int pass = 0; pass < 4; pass++) {
                uint32_t wd = ijw[pass];
                int ii = (wd >> sh) & 0xFF;
                int jj = (wd >> (sh + 8)) & 0xFF;
                int rw = (w << 3) + (pass << 1) + rhalf;
                float4 a4 = *(const float4*)(sT + (ii << 6) + p4l);
                float4 b4 = *(const float4*)(sT + (jj << 6) + p4l);
                uint4 r;
                r.x = cvt_tf32(a4.x * b4.x);
                r.y = cvt_tf32(a4.y * b4.y);
                r.z = cvt_tf32(a4.z * b4.z);
                r.w = cvt_tf32(a4.w * b4.w);
                *(uint4*)(pfn + rw * 72 + p4l) = r;
            }
        }

        // 3. mma over this warp's 4 k8 steps of chunk g
        #pragma unroll
        for (int kk = 0; kk < 4; kk++) {
            int k0 = (kk + (ksel << 2)) << 3;
            uint32_t a[2][4];
            #pragma unroll
            for (int mt = 0; mt < 2; mt++) {
                int prw = pbase + (mt << 4) + (gid << 1);
                uint2 lo = *(const uint2*)(pfc + (k0 + tig) * 72 + prw);
                uint2 hi = *(const uint2*)(pfc + (k0 + 4 + tig) * 72 + prw);
                a[mt][0] = lo.x; a[mt][1] = lo.y;
                a[mt][2] = hi.x; a[mt][3] = hi.y;
            }
            uint32_t bb[4][2];
            #pragma unroll
            for (int nt = 0; nt < 4; nt++) {
                int nc = nbase + (nt << 3) + gid;
                uint2 bv = *(const uint2*)(sBc + nc * 72 + k0 + (tig << 1));
                bb[nt][0] = bv.x; bb[nt][1] = bv.y;
            }
            #pragma unroll
            for (int mt = 0; mt < 2; mt++)
                #pragma unroll
                for (int nt = 0; nt < 4; nt++)
                    mma8(d[mt][nt], a[mt], bb[nt]);
        }

        // 4. store B(g+1) into nxt buffer
        if (more) {
            float* sBn = sB + nxt * BBUF;
            #pragma unroll
            for (int i = 0; i < 4; i++) {
                int idx = tid + (i << 8);
                int n = idx >> 4, k4 = (idx & 15) << 2;
                *(float4*)(sBn + n * 72 + k4) = breg[i];
            }
        }
        __syncthreads();
    }

    // ---- merge k-halves into zt[pos][68] (pf region) ----
    // accumulator (mt,nt,q) maps: rows pbase_pos + mt*16 + gid (+8), cols as before
    float* zt = (float*)pfu;
    const int prow = ((w & 1) << 5);     // position base of m-group
    if (ksel == 1) {
        #pragma unroll
        for (int mt = 0; mt < 2; mt++) {
            int r0 = prow + (mt << 4) + gid;
            #pragma unroll
            for (int nt = 0; nt < 4; nt++) {
                int col = nbase + (nt << 3) + (tig << 1);
                zt[r0 * 68 + col]           = d[mt][nt][0];
                zt[r0 * 68 + col + 1]       = d[mt][nt][1];
                zt[(r0 + 8) * 68 + col]     = d[mt][nt][2];
                zt[(r0 + 8) * 68 + col + 1] = d[mt][nt][3];
            }
        }
    }
    // stage fc1T into t region: sF[c][68]
    float* sF = sT;
    #pragma unroll
    for (int it = 0; it < 16; it++) {
        int idx = tid + (it << 8);
        sF[(idx >> 6) * 68 + (idx & 63)] = g_fc1T[idx];
    }
    __syncthreads();
    if (ksel == 0) {
        #pragma unroll
        for (int mt = 0; mt < 2; mt++) {
            int r0 = prow + (mt << 4) + gid;
            #pragma unroll
            for (int nt = 0; nt < 4; nt++) {
                int col = nbase + (nt << 3) + (tig << 1);
                zt[r0 * 68 + col]           += d[mt][nt][0] + sP[col];
                zt[r0 * 68 + col + 1]       += d[mt][nt][1] + sP[col + 1];
                zt[(r0 + 8) * 68 + col]     += d[mt][nt][2] + sP[col];
                zt[(r0 + 8) * 68 + col + 1] += d[mt][nt][3] + sP[col + 1];
            }
        }
    }
    __syncthreads();

    // LayerNorm over 64 channels: 4 threads per position
    {
        int pos = tid >> 2, q = tid & 3;
        float* zr = zt + pos * 68 + (q << 4);
        float s = 0.f, s2 = 0.f;
        #pragma unroll
        for (int c = 0; c < 16; c++) { float v = zr[c]; s += v; s2 += v * v; }
        s  += __shfl_xor_sync(0xffffffffu, s, 1);
        s2 += __shfl_xor_sync(0xffffffffu, s2, 1);
        s  += __shfl_xor_sync(0xffffffffu, s, 2);
        s2 += __shfl_xor_sync(0xffffffffu, s2, 2);
        float mu   = s  * (1.0f / 64.0f);
        float var  = s2 * (1.0f / 64.0f) - mu * mu;
        float rstd = rsqrtf(var + 1e-5f);
        #pragma unroll
        for (int c = 0; c < 16; c++) {
            int cc = (q << 4) + c;
            zr[c] = (zr[c] - mu) * rstd * sP[64 + cc] + sP[128 + cc];
        }
    }
    __syncthreads();

    // fc1 (64x64) + GELU: thread tile 4 pos x 4 out; zo in B region [o][68]
    float* zo = sB;
    {
        int tx = tid & 15, ty = tid >> 4;
        int ob = tx << 2, pb = ty << 2;
        float a2[4][4];
        #pragma unroll
        for (int r = 0; r < 4; r++)
            #pragma unroll
            for (int j = 0; j < 4; j++) a2[r][j] = 0.f;
        #pragma unroll 8
        for (int c = 0; c < DIMO; c++) {
            float4 f = *(const float4*)(sF + c * 68 + ob);
            #pragma unroll
            for (int r = 0; r < 4; r++) {
                float z = zt[(pb + r) * 68 + c];
                a2[r][0] += z * f.x; a2[r][1] += z * f.y;
                a2[r][2] += z * f.z; a2[r][3] += z * f.w;
            }
        }
        #pragma unroll
        for (int r = 0; r < 4; r++)
            #pragma unroll
            for (int j = 0; j < 4; j++) {
                float v = a2[r][j] + sP[192 + ob + j];
                v = 0.5f * v * (1.0f + erff(v * 0.70710678118654752f));
                zo[(ob + j) * 68 + pb + r] = v;
            }
    }
    __syncthreads();

    // coalesced store
    {
        float* ob = out + (size_t)b * DIMO * LTOT + p0;
        #pragma unroll
        for (int it = 0; it < 16; it++) {
            int idx = tid + (it << 8);
            int o = idx >> 6, pos = idx & 63;
            ob[(size_t)o * LTOT + pos] = zo[o * 68 + pos];
        }
    }
}

// ------------------------------- launch -----------------------------------
extern "C" void kernel_launch(void* const* d_in, const int* in_sizes, int n_in,
                              void* d_out, int out_size) {
    const float* x    = (const float*)d_in[0];
    const float* n1w  = (const float*)d_in[1];
    const float* n1b  = (const float*)d_in[2];
    const float* drw  = (const float*)d_in[3];
    const float* drb  = (const float*)d_in[4];
    const float* n2w  = (const float*)d_in[5];
    const float* n2b  = (const float*)d_in[6];
    const float* f1w  = (const float*)d_in[7];
    const float* f1b  = (const float*)d_in[8];
    float* out = (float*)d_out;

    const int SMEM_LN   = (128 * 129 + 3 * 128 + 4) * 4;   // 67600
    const int SMEM_MAIN = FTOT * 4;                        // 108544

    cudaFuncSetAttribute(k_ln,   cudaFuncAttributeMaxDynamicSharedMemorySize, SMEM_LN);
    cudaFuncSetAttribute(k_main, cudaFuncAttributeMaxDynamicSharedMemorySize, SMEM_MAIN);

    k_init<<<64, 256>>>(drw, f1w);
    k_mid<<<BATCH, 128>>>(x, n1w, n1b);
    k_ln<<<(BATCH * LTOT) / 128, 128, SMEM_LN>>>(x, n1w, n1b);
    k_main<<<(BATCH * LTOT) / POSB, 256, SMEM_MAIN>>>(drb, n2w, n2b, f1b, out);
}